// round 10
// baseline (speedup 1.0000x reference)
#include <cuda_runtime.h>
#include <cstdint>

#define BB 64
#define LL 1024
#define SS 8
#define DD 128
#define BL (BB*LL)          // 65536
#define NELEM (2*BL)        // 131072 element-sides
#define KEYSPACE 16384      // id*8 + (snap-1), id < 2000 -> key < 16000

// ---- device scratch ----
__device__ float4 g_hot[128*32];       // hot joint table (s<8, cx<4, cy<4), 64KB

// ============================================================
// Direct evaluation of one output row for (s, cx, cy).
// Warp-collective; lane holds float4 covering d' = 4*lane .. 4*lane+3.
// ============================================================
__device__ __noinline__ float4 elem_direct(int s, int cx, int cy, int lane,
                              const float* __restrict__ aw1,
                              const float* __restrict__ ab1,
                              const float* __restrict__ aw2,
                              const float* __restrict__ ab2,
                              const float* __restrict__ ew1,
                              const float* __restrict__ eb1,
                              const float* __restrict__ ew2,
                              const float* __restrict__ eb2) {
    float fx = (float)cx, fy = (float)cy;
    float a0 = 0.f, a1 = 0.f;
#pragma unroll
    for (int m = 0; m < 4; ++m) {
        int d = lane + 32*m;
        float w = __ldg(&aw1[s*DD + d]);
        float b = __ldg(&ab1[d]);
        float h = fmaxf(fmaf(fx, w, b), 0.f) + fmaxf(fmaf(fy, w, b), 0.f);
        a0 = fmaf(h, __ldg(&aw2[2*d + 0]), a0);
        a1 = fmaf(h, __ldg(&aw2[2*d + 1]), a1);
    }
#pragma unroll
    for (int off = 16; off; off >>= 1) {
        a0 += __shfl_xor_sync(0xffffffffu, a0, off);
        a1 += __shfl_xor_sync(0xffffffffu, a1, off);
    }
    float y0 = fmaf(0.5f, a0, __ldg(&ab2[0]));
    float y1 = fmaf(0.5f, a1, __ldg(&ab2[1]));

    float4 e2 = __ldg(&((const float4*)eb2)[lane]);
    float4 acc;
    acc.x = 2.f*e2.x; acc.y = 2.f*e2.y; acc.z = 2.f*e2.z; acc.w = 2.f*e2.w;
    const float4* W2 = (const float4*)ew2;
#pragma unroll 4
    for (int d = 0; d < DD; ++d) {
        float w = __ldg(&ew1[d]);
        float b = __ldg(&eb1[d]);
        float h = fmaxf(fmaf(y0, w, b), 0.f) + fmaxf(fmaf(y1, w, b), 0.f);
        float4 w2 = __ldg(&W2[d*32 + lane]);
        acc.x = fmaf(h, w2.x, acc.x);
        acc.y = fmaf(h, w2.y, acc.y);
        acc.z = fmaf(h, w2.z, acc.z);
        acc.w = fmaf(h, w2.w, acc.w);
    }
    return acc;
}

// ============================================================
// Hot-table generator: 128 warps, one row each (grid 4 x 1024).
// ============================================================
__global__ __launch_bounds__(1024, 1)
void k_hot(const float* __restrict__ aw1, const float* __restrict__ ab1,
           const float* __restrict__ aw2, const float* __restrict__ ab2,
           const float* __restrict__ ew1, const float* __restrict__ eb1,
           const float* __restrict__ ew2, const float* __restrict__ eb2) {
    int wid = threadIdx.x >> 5, lane = threadIdx.x & 31;
    int ce = blockIdx.x*32 + wid;        // 0..127
    int s  = ce >> 4;
    int cx = (ce >> 2) & 3;
    int cy = ce & 3;
    g_hot[ce*32 + lane] = elem_direct(s, cx, cy, lane,
                                      aw1, ab1, aw2, ab2, ew1, eb1, ew2, eb2);
}

// ============================================================
// Fused count + gather kernel. 4 blocks per batch (grid 256).
// Each block: full-batch smem histogram (redundant x4), then
// gathers + stores its 512-element quarter directly from smem counts.
// ============================================================
__global__ __launch_bounds__(1024, 2)
void k_all(const int* __restrict__ sid, const int* __restrict__ did,
           const int* __restrict__ ssn, const int* __restrict__ dsn,
           const float* __restrict__ aw1, const float* __restrict__ ab1,
           const float* __restrict__ aw2, const float* __restrict__ ab2,
           const float* __restrict__ ew1, const float* __restrict__ eb1,
           const float* __restrict__ ew2, const float* __restrict__ eb2,
           float4* __restrict__ out) {
    extern __shared__ uint32_t tab[];           // 16384 words = 64KB
    uint32_t* tabS = tab;                       // KEYSPACE/2 packed u16x2
    uint32_t* tabD = tab + KEYSPACE/2;
    int tid  = threadIdx.x;
    int lane = tid & 31;
    int wid  = tid >> 5;
    int b = blockIdx.x >> 2;
    int q = blockIdx.x & 3;

    // ---- zero histogram ----
    uint4* z = (uint4*)tab;
#pragma unroll
    for (int i = 0; i < 4; ++i) z[tid + i*1024] = make_uint4(0,0,0,0);
    __syncthreads();

    // ---- full-batch histogram (1 pos per thread) ----
    int gi = b*LL + tid;
    unsigned k1 = (unsigned)(sid[gi]*8 + (ssn[gi]-1));
    unsigned k2 = (unsigned)(did[gi]*8 + (dsn[gi]-1));
    k1 = min(k1, (unsigned)(KEYSPACE-1));
    k2 = min(k2, (unsigned)(KEYSPACE-1));
    atomicAdd(&tabS[k1>>1], 1u << ((k1&1)*16));
    atomicAdd(&tabD[k2>>1], 1u << ((k2&1)*16));
    __syncthreads();

    // ---- gather + store: this block's 512 element-sides ----
    // warp w handles elements j = w*16 .. w*16+15 of the block list:
    //   j < 256  -> src position p = q*256 + j
    //   j >= 256 -> dst position p = q*256 + (j-256)
    int jbase = wid * 16;
    int s = 0, cx = 0, cy = 0;
    bool hot = true;
    size_t erow = 0;
    if (lane < 16) {
        int j = jbase + lane;
        int side = j >> 8;                  // 0 = src, 1 = dst
        int p = q*256 + (j & 255);
        int pos = b*LL + p;
        unsigned key;
        if (side == 0) key = min((unsigned)(sid[pos]*8 + (ssn[pos]-1)), (unsigned)(KEYSPACE-1));
        else           key = min((unsigned)(did[pos]*8 + (dsn[pos]-1)), (unsigned)(KEYSPACE-1));
        uint32_t own   = ((side ? tabD : tabS)[key>>1] >> ((key&1)*16)) & 0xFFFFu;
        uint32_t cross = ((side ? tabS : tabD)[key>>1] >> ((key&1)*16)) & 0xFFFFu;
        if (key < 8) { own = 0; cross = 0; }     // id == 0 -> invalid
        cx = (int)own; cy = (int)cross; s = (int)(key & 7u);
        hot = ((cx | cy) < 4);
        erow = (size_t)(side*BL + b*LL + p);
    }
    int idx = (s << 4) | (cx << 2) | cy;
    unsigned hm = __ballot_sync(0xffffffffu, hot);

    if (hm == 0xffffffffu) {
#pragma unroll
        for (int i = 0; i < 16; ++i) {
            int id_i = __shfl_sync(0xffffffffu, idx, i);
            size_t er = (size_t)__shfl_sync(0xffffffffu, (unsigned)erow, i);
            float4 r = g_hot[id_i*32 + lane];
            __stcs(&out[er*32 + lane], r);
        }
    } else {
        for (int i = 0; i < 16; ++i) {
            size_t er = (size_t)__shfl_sync(0xffffffffu, (unsigned)erow, i);
            float4 r;
            if ((hm >> i) & 1) {
                int id_i = __shfl_sync(0xffffffffu, idx, i);
                r = g_hot[id_i*32 + lane];
            } else {
                int si  = __shfl_sync(0xffffffffu, s, i);
                int cxi = __shfl_sync(0xffffffffu, cx, i);
                int cyi = __shfl_sync(0xffffffffu, cy, i);
                r = elem_direct(si, cxi, cyi, lane,
                                aw1, ab1, aw2, ab2, ew1, eb1, ew2, eb2);
            }
            __stcs(&out[er*32 + lane], r);
        }
    }
}

// ============================================================
extern "C" void kernel_launch(void* const* d_in, const int* in_sizes, int n_in,
                              void* d_out, int out_size) {
    const int*   sid = (const int*)d_in[0];
    const int*   did = (const int*)d_in[1];
    const int*   ssn = (const int*)d_in[2];
    const int*   dsn = (const int*)d_in[3];
    const float* aw1 = (const float*)d_in[5];
    const float* ab1 = (const float*)d_in[6];
    const float* aw2 = (const float*)d_in[7];
    const float* ab2 = (const float*)d_in[8];
    const float* ew1 = (const float*)d_in[9];
    const float* eb1 = (const float*)d_in[10];
    const float* ew2 = (const float*)d_in[11];
    const float* eb2 = (const float*)d_in[12];
    float4* out = (float4*)d_out;

    size_t allSmem = (size_t)KEYSPACE * sizeof(uint32_t);   // 64 KB
    cudaFuncSetAttribute(k_all, cudaFuncAttributeMaxDynamicSharedMemorySize, (int)allSmem);

    k_hot<<<4, 1024>>>(aw1, ab1, aw2, ab2, ew1, eb1, ew2, eb2);
    k_all<<<256, 1024, allSmem>>>(sid, did, ssn, dsn,
                                  aw1, ab1, aw2, ab2, ew1, eb1, ew2, eb2, out);
}

// round 11
// speedup vs baseline: 1.0082x; 1.0082x over previous
#include <cuda_runtime.h>
#include <cstdint>

#define BB 64
#define LL 1024
#define SS 8
#define DD 128
#define BL (BB*LL)          // 65536
#define NELEM (2*BL)        // 131072 element-sides
#define KEYSPACE 16384      // id*8 + (snap-1), id < 2000 -> key < 16000

// ---- device scratch ----
__device__ uint32_t g_cnt[NELEM];      // packed: cx | cy<<11 | s<<22
__device__ float4   g_hot[128*32];     // hot joint table (s<8, cx<4, cy<4), 64KB

// ============================================================
// Direct evaluation of one output row for (s, cx, cy).
// Warp-collective; lane holds float4 covering d' = 4*lane .. 4*lane+3.
// __noinline__ keeps the rare path's registers out of hot kernels.
// ============================================================
__device__ __noinline__ float4 elem_direct(int s, int cx, int cy, int lane,
                              const float* __restrict__ aw1,
                              const float* __restrict__ ab1,
                              const float* __restrict__ aw2,
                              const float* __restrict__ ab2,
                              const float* __restrict__ ew1,
                              const float* __restrict__ eb1,
                              const float* __restrict__ ew2,
                              const float* __restrict__ eb2) {
    float fx = (float)cx, fy = (float)cy;
    float a0 = 0.f, a1 = 0.f;
#pragma unroll
    for (int m = 0; m < 4; ++m) {
        int d = lane + 32*m;
        float w = __ldg(&aw1[s*DD + d]);
        float b = __ldg(&ab1[d]);
        float h = fmaxf(fmaf(fx, w, b), 0.f) + fmaxf(fmaf(fy, w, b), 0.f);
        a0 = fmaf(h, __ldg(&aw2[2*d + 0]), a0);
        a1 = fmaf(h, __ldg(&aw2[2*d + 1]), a1);
    }
#pragma unroll
    for (int off = 16; off; off >>= 1) {
        a0 += __shfl_xor_sync(0xffffffffu, a0, off);
        a1 += __shfl_xor_sync(0xffffffffu, a1, off);
    }
    float y0 = fmaf(0.5f, a0, __ldg(&ab2[0]));
    float y1 = fmaf(0.5f, a1, __ldg(&ab2[1]));

    float4 e2 = __ldg(&((const float4*)eb2)[lane]);
    float4 acc;
    acc.x = 2.f*e2.x; acc.y = 2.f*e2.y; acc.z = 2.f*e2.z; acc.w = 2.f*e2.w;
    const float4* W2 = (const float4*)ew2;
#pragma unroll 4
    for (int d = 0; d < DD; ++d) {
        float w = __ldg(&ew1[d]);
        float b = __ldg(&eb1[d]);
        float h = fmaxf(fmaf(y0, w, b), 0.f) + fmaxf(fmaf(y1, w, b), 0.f);
        float4 w2 = __ldg(&W2[d*32 + lane]);
        acc.x = fmaf(h, w2.x, acc.x);
        acc.y = fmaf(h, w2.y, acc.y);
        acc.z = fmaf(h, w2.z, acc.z);
        acc.w = fmaf(h, w2.w, acc.w);
    }
    return acc;
}

// ============================================================
// Fused kernel. Block roles by blockIdx.x:
//   [0,64)  : per-batch histogram count (64KB smem)
//   [64,68) : hot joint table, one row per warp (direct eval)
// ============================================================
__global__ __launch_bounds__(1024, 1)
void k_fused(const int* __restrict__ sid, const int* __restrict__ did,
             const int* __restrict__ ssn, const int* __restrict__ dsn,
             const float* __restrict__ aw1, const float* __restrict__ ab1,
             const float* __restrict__ aw2, const float* __restrict__ ab2,
             const float* __restrict__ ew1, const float* __restrict__ eb1,
             const float* __restrict__ ew2, const float* __restrict__ eb2) {
    extern __shared__ uint32_t smraw[];
    int bid = blockIdx.x;
    int tid = threadIdx.x;

    if (bid < 64) {
        // ---------------- count section ----------------
        uint32_t* tabS = smraw;                // KEYSPACE/2 words
        uint32_t* tabD = smraw + KEYSPACE/2;
        int b = bid;
        uint4* z = (uint4*)smraw;
#pragma unroll
        for (int i = 0; i < 4; ++i) z[tid + i*1024] = make_uint4(0,0,0,0);
        __syncthreads();

        int i = b*LL + tid;
        unsigned k1 = (unsigned)(sid[i]*8 + (ssn[i]-1));
        unsigned k2 = (unsigned)(did[i]*8 + (dsn[i]-1));
        k1 = min(k1, (unsigned)(KEYSPACE-1));
        k2 = min(k2, (unsigned)(KEYSPACE-1));
        atomicAdd(&tabS[k1>>1], 1u << ((k1&1)*16));
        atomicAdd(&tabD[k2>>1], 1u << ((k2&1)*16));
        __syncthreads();

        uint32_t cxS = (tabS[k1>>1] >> ((k1&1)*16)) & 0xFFFFu;
        uint32_t cyS = (tabD[k1>>1] >> ((k1&1)*16)) & 0xFFFFu;
        uint32_t cxD = (tabD[k2>>1] >> ((k2&1)*16)) & 0xFFFFu;
        uint32_t cyD = (tabS[k2>>1] >> ((k2&1)*16)) & 0xFFFFu;
        if (k1 < 8) { cxS = 0; cyS = 0; }     // id == 0 -> invalid
        if (k2 < 8) { cxD = 0; cyD = 0; }
        g_cnt[     b*LL + tid] = cxS | (cyS << 11) | ((k1 & 7u) << 22);
        g_cnt[BL + b*LL + tid] = cxD | (cyD << 11) | ((k2 & 7u) << 22);

    } else {
        // ---------------- hot-table section ----------------
        int wid  = tid >> 5;
        int lane = tid & 31;
        int ce = (bid - 64)*32 + wid;         // 0..127
        int s  = ce >> 4;
        int cx = (ce >> 2) & 3;
        int cy = ce & 3;
        g_hot[ce*32 + lane] = elem_direct(s, cx, cy, lane,
                                          aw1, ab1, aw2, ab2,
                                          ew1, eb1, ew2, eb2);
    }
}

// ============================================================
// Main kernel: chunk-of-32 per warp. Coalesced pk load, one hotness
// ballot per chunk, fully-unrolled L1-cached gather + coalesced store.
// Rare cold elements: warp-collective direct MLP evaluation.
// __launch_bounds__(256,8) forces regs<=32 -> 64 warps/SM.
// ============================================================
__global__ __launch_bounds__(256, 8)
void k_main(const float* __restrict__ aw1, const float* __restrict__ ab1,
            const float* __restrict__ aw2, const float* __restrict__ ab2,
            const float* __restrict__ ew1, const float* __restrict__ eb1,
            const float* __restrict__ ew2, const float* __restrict__ eb2,
            float4* __restrict__ out) {
    int wid  = threadIdx.x >> 5;
    int lane = threadIdx.x & 31;
    int chunk = blockIdx.x*8 + wid;          // 0..4095 (grid 512)
    int base  = chunk << 5;                  // element base

    uint32_t pk = g_cnt[base + lane];        // coalesced, 1 transaction/warp
    int cx = pk & 0x7FF;
    int cy = (pk >> 11) & 0x7FF;
    int s  = pk >> 22;
    bool hot = ((cx | cy) < 4);
    int idx = (s << 4) | (cx << 2) | cy;     // valid when hot
    unsigned hm = __ballot_sync(0xffffffffu, hot);

    if (hm == 0xffffffffu) {
#pragma unroll
        for (int i = 0; i < 32; ++i) {
            int id_i = __shfl_sync(0xffffffffu, idx, i);
            out[(size_t)(base + i)*32 + lane] = g_hot[id_i*32 + lane];
        }
    } else {
        for (int i = 0; i < 32; ++i) {
            if ((hm >> i) & 1) {
                int id_i = __shfl_sync(0xffffffffu, idx, i);
                out[(size_t)(base + i)*32 + lane] = g_hot[id_i*32 + lane];
            } else {
                int si  = __shfl_sync(0xffffffffu, s, i);
                int cxi = __shfl_sync(0xffffffffu, cx, i);
                int cyi = __shfl_sync(0xffffffffu, cy, i);
                out[(size_t)(base + i)*32 + lane] =
                    elem_direct(si, cxi, cyi, lane,
                                aw1, ab1, aw2, ab2, ew1, eb1, ew2, eb2);
            }
        }
    }
}

// ============================================================
extern "C" void kernel_launch(void* const* d_in, const int* in_sizes, int n_in,
                              void* d_out, int out_size) {
    const int*   sid = (const int*)d_in[0];
    const int*   did = (const int*)d_in[1];
    const int*   ssn = (const int*)d_in[2];
    const int*   dsn = (const int*)d_in[3];
    const float* aw1 = (const float*)d_in[5];
    const float* ab1 = (const float*)d_in[6];
    const float* aw2 = (const float*)d_in[7];
    const float* ab2 = (const float*)d_in[8];
    const float* ew1 = (const float*)d_in[9];
    const float* eb1 = (const float*)d_in[10];
    const float* ew2 = (const float*)d_in[11];
    const float* eb2 = (const float*)d_in[12];
    float4* out = (float4*)d_out;

    size_t fusedSmem = (size_t)KEYSPACE * sizeof(uint32_t);   // 64 KB
    cudaFuncSetAttribute(k_fused, cudaFuncAttributeMaxDynamicSharedMemorySize, (int)fusedSmem);

    k_fused<<<68, 1024, fusedSmem>>>(sid, did, ssn, dsn,
                                     aw1, ab1, aw2, ab2, ew1, eb1, ew2, eb2);
    k_main<<<512, 256>>>(aw1, ab1, aw2, ab2, ew1, eb1, ew2, eb2, out);
}

// round 12
// speedup vs baseline: 1.0801x; 1.0714x over previous
#include <cuda_runtime.h>
#include <cstdint>

#define BB 64
#define LL 1024
#define SS 8
#define DD 128
#define BL (BB*LL)          // 65536
#define NELEM (2*BL)        // 131072 element-sides
#define KEYSPACE 16384      // id*8 + (snap-1), id < 2000 -> key < 16000

// ---- device scratch ----
__device__ uint32_t g_cnt[NELEM];      // packed: cx | cy<<11 | s<<22
__device__ float4   g_hot[128*32];     // hot joint table (s<8, cx<4, cy<4), 64KB

// ============================================================
// Direct evaluation of one output row for (s, cx, cy).
// Warp-collective; lane holds float4 covering d' = 4*lane .. 4*lane+3.
// __noinline__ keeps the rare path's registers out of hot kernels.
// ============================================================
__device__ __noinline__ float4 elem_direct(int s, int cx, int cy, int lane,
                              const float* __restrict__ aw1,
                              const float* __restrict__ ab1,
                              const float* __restrict__ aw2,
                              const float* __restrict__ ab2,
                              const float* __restrict__ ew1,
                              const float* __restrict__ eb1,
                              const float* __restrict__ ew2,
                              const float* __restrict__ eb2) {
    float fx = (float)cx, fy = (float)cy;
    float a0 = 0.f, a1 = 0.f;
#pragma unroll
    for (int m = 0; m < 4; ++m) {
        int d = lane + 32*m;
        float w = __ldg(&aw1[s*DD + d]);
        float b = __ldg(&ab1[d]);
        float h = fmaxf(fmaf(fx, w, b), 0.f) + fmaxf(fmaf(fy, w, b), 0.f);
        a0 = fmaf(h, __ldg(&aw2[2*d + 0]), a0);
        a1 = fmaf(h, __ldg(&aw2[2*d + 1]), a1);
    }
#pragma unroll
    for (int off = 16; off; off >>= 1) {
        a0 += __shfl_xor_sync(0xffffffffu, a0, off);
        a1 += __shfl_xor_sync(0xffffffffu, a1, off);
    }
    float y0 = fmaf(0.5f, a0, __ldg(&ab2[0]));
    float y1 = fmaf(0.5f, a1, __ldg(&ab2[1]));

    float4 e2 = __ldg(&((const float4*)eb2)[lane]);
    float4 acc;
    acc.x = 2.f*e2.x; acc.y = 2.f*e2.y; acc.z = 2.f*e2.z; acc.w = 2.f*e2.w;
    const float4* W2 = (const float4*)ew2;
#pragma unroll 4
    for (int d = 0; d < DD; ++d) {
        float w = __ldg(&ew1[d]);
        float b = __ldg(&eb1[d]);
        float h = fmaxf(fmaf(y0, w, b), 0.f) + fmaxf(fmaf(y1, w, b), 0.f);
        float4 w2 = __ldg(&W2[d*32 + lane]);
        acc.x = fmaf(h, w2.x, acc.x);
        acc.y = fmaf(h, w2.y, acc.y);
        acc.z = fmaf(h, w2.z, acc.z);
        acc.w = fmaf(h, w2.w, acc.w);
    }
    return acc;
}

// ============================================================
// Fused kernel. Block roles by blockIdx.x:
//   [0,64)  : per-batch histogram count (64KB smem)
//   [64,68) : hot joint table, one row per warp (direct eval)
// ============================================================
__global__ __launch_bounds__(1024, 1)
void k_fused(const int* __restrict__ sid, const int* __restrict__ did,
             const int* __restrict__ ssn, const int* __restrict__ dsn,
             const float* __restrict__ aw1, const float* __restrict__ ab1,
             const float* __restrict__ aw2, const float* __restrict__ ab2,
             const float* __restrict__ ew1, const float* __restrict__ eb1,
             const float* __restrict__ ew2, const float* __restrict__ eb2) {
    extern __shared__ uint32_t smraw[];
    int bid = blockIdx.x;
    int tid = threadIdx.x;

    if (bid < 64) {
        // ---------------- count section ----------------
        uint32_t* tabS = smraw;                // KEYSPACE/2 words
        uint32_t* tabD = smraw + KEYSPACE/2;
        int b = bid;
        uint4* z = (uint4*)smraw;
#pragma unroll
        for (int i = 0; i < 4; ++i) z[tid + i*1024] = make_uint4(0,0,0,0);
        __syncthreads();

        int i = b*LL + tid;
        unsigned k1 = (unsigned)(sid[i]*8 + (ssn[i]-1));
        unsigned k2 = (unsigned)(did[i]*8 + (dsn[i]-1));
        k1 = min(k1, (unsigned)(KEYSPACE-1));
        k2 = min(k2, (unsigned)(KEYSPACE-1));
        atomicAdd(&tabS[k1>>1], 1u << ((k1&1)*16));
        atomicAdd(&tabD[k2>>1], 1u << ((k2&1)*16));
        __syncthreads();

        uint32_t cxS = (tabS[k1>>1] >> ((k1&1)*16)) & 0xFFFFu;
        uint32_t cyS = (tabD[k1>>1] >> ((k1&1)*16)) & 0xFFFFu;
        uint32_t cxD = (tabD[k2>>1] >> ((k2&1)*16)) & 0xFFFFu;
        uint32_t cyD = (tabS[k2>>1] >> ((k2&1)*16)) & 0xFFFFu;
        if (k1 < 8) { cxS = 0; cyS = 0; }     // id == 0 -> invalid
        if (k2 < 8) { cxD = 0; cyD = 0; }
        g_cnt[     b*LL + tid] = cxS | (cyS << 11) | ((k1 & 7u) << 22);
        g_cnt[BL + b*LL + tid] = cxD | (cyD << 11) | ((k2 & 7u) << 22);

    } else {
        // ---------------- hot-table section ----------------
        int wid  = tid >> 5;
        int lane = tid & 31;
        int ce = (bid - 64)*32 + wid;         // 0..127
        int s  = ce >> 4;
        int cx = (ce >> 2) & 3;
        int cy = ce & 3;
        g_hot[ce*32 + lane] = elem_direct(s, cx, cy, lane,
                                          aw1, ab1, aw2, ab2,
                                          ew1, eb1, ew2, eb2);
    }
}

// ============================================================
// Main kernel: ONE WARP PER ELEMENT (131072 warps, grid 16384).
// Broadcast pk load -> decode -> L1-hit g_hot row gather -> STG.128.
// Rare cold elements: warp-collective direct MLP (warp-uniform branch).
// ============================================================
__global__ __launch_bounds__(256, 8)
void k_main(const float* __restrict__ aw1, const float* __restrict__ ab1,
            const float* __restrict__ aw2, const float* __restrict__ ab2,
            const float* __restrict__ ew1, const float* __restrict__ eb1,
            const float* __restrict__ ew2, const float* __restrict__ eb2,
            float4* __restrict__ out) {
    int lane = threadIdx.x & 31;
    int e = blockIdx.x*8 + (threadIdx.x >> 5);   // element id == warp id

    uint32_t pk = g_cnt[e];                      // broadcast: 1 wavefront/warp
    int cx = pk & 0x7FF;
    int cy = (pk >> 11) & 0x7FF;
    int s  = pk >> 22;

    float4 r;
    if ((cx | cy) < 4) {                         // warp-uniform
        int idx = (s << 4) | (cx << 2) | cy;
        r = g_hot[idx*32 + lane];
    } else {
        r = elem_direct(s, cx, cy, lane,
                        aw1, ab1, aw2, ab2, ew1, eb1, ew2, eb2);
    }
    __stcs(&out[(size_t)e*32 + lane], r);
}

// ============================================================
extern "C" void kernel_launch(void* const* d_in, const int* in_sizes, int n_in,
                              void* d_out, int out_size) {
    const int*   sid = (const int*)d_in[0];
    const int*   did = (const int*)d_in[1];
    const int*   ssn = (const int*)d_in[2];
    const int*   dsn = (const int*)d_in[3];
    const float* aw1 = (const float*)d_in[5];
    const float* ab1 = (const float*)d_in[6];
    const float* aw2 = (const float*)d_in[7];
    const float* ab2 = (const float*)d_in[8];
    const float* ew1 = (const float*)d_in[9];
    const float* eb1 = (const float*)d_in[10];
    const float* ew2 = (const float*)d_in[11];
    const float* eb2 = (const float*)d_in[12];
    float4* out = (float4*)d_out;

    size_t fusedSmem = (size_t)KEYSPACE * sizeof(uint32_t);   // 64 KB
    cudaFuncSetAttribute(k_fused, cudaFuncAttributeMaxDynamicSharedMemorySize, (int)fusedSmem);

    k_fused<<<68, 1024, fusedSmem>>>(sid, did, ssn, dsn,
                                     aw1, ab1, aw2, ab2, ew1, eb1, ew2, eb2);
    k_main<<<NELEM/8, 256>>>(aw1, ab1, aw2, ab2, ew1, eb1, ew2, eb2, out);
}